// round 1
// baseline (speedup 1.0000x reference)
#include <cuda_runtime.h>

// ChannelExchangeWithConv: N=1, C=128, H=W=512, p=2
// out_lst = copy(lst); out_lst[::2] = W2 @ gui[::2] + b2
// out_gui = copy(gui); out_gui[::2] = W1 @ lst[::2] + b1
// d_out = [out_lst (128*512*512) | out_gui (128*512*512)] fp32

#define HW   262144          // H*W
#define TP   256             // pixels per CTA tile
#define NCTA (HW / TP)       // 1024
#define CH   64              // channels per conv (C/p)

__device__ __forceinline__ unsigned long long pk2(float x, float y) {
    unsigned long long r;
    asm("mov.b64 %0, {%1, %2};" : "=l"(r) : "f"(x), "f"(y));
    return r;
}

// packed 2-wide fp32 fma: acc = a*b + acc  (two independent fp32 lanes)
#define FMA2(acc, a, b) \
    asm("fma.rn.f32x2 %0, %1, %2, %0;" : "+l"(acc) : "l"(a), "l"(b))

__global__ __launch_bounds__(256, 2)
void cx_kernel(const float* __restrict__ lst, const float* __restrict__ gui,
               const float* __restrict__ w1,  const float* __restrict__ b1,
               const float* __restrict__ w2,  const float* __restrict__ b2,
               float* __restrict__ out)
{
    extern __shared__ float smem[];
    float*  Xs = smem;                                  // [64][TP] conv-input tile
    float2* Wd = (float2*)(smem + CH * TP);             // [c][o] duplicated weights
    float*  Bs = (float*)(Wd + CH * CH);                // [64] bias

    const int   dir  = blockIdx.y;                      // 0: out_lst, 1: out_gui
    const float* xin  = dir ? lst : gui;                // conv input (even channels)
    const float* cpin = dir ? gui : lst;                // passthrough src (odd channels)
    const float* W    = dir ? w1 : w2;
    const float* B    = dir ? b1 : b2;
    float* oo = out + (size_t)dir * 128 * HW;

    const int pix0 = blockIdx.x * TP;
    const int tid  = threadIdx.x;

    // --- stage weights, duplicated {w,w}, transposed to [c][o] for broadcast reads ---
    // global read is scattered (stride-64) but it's 16KB, L2-hot across 2048 CTAs.
    #pragma unroll
    for (int i = 0; i < 16; i++) {
        int idx = i * 256 + tid;        // 0..4095
        int c = idx >> 6;
        int o = idx & 63;
        float v = W[o * CH + c];        // W is [o][c] row-major
        Wd[c * CH + o] = make_float2(v, v);   // conflict-free STS (o consecutive per lane)
    }
    if (tid < CH) Bs[tid] = B[tid];

    // --- stage even channels of xin into smem; stream odd-channel passthrough ---
    #pragma unroll
    for (int i = 0; i < 16; i++) {
        int idx = i * 256 + tid;        // float4 units over [64][64]
        int row = idx >> 6;             // 0..63  (masked-channel index)
        int col = (idx & 63) << 2;      // 0..252 (float offset in tile)
        float4 xv = *(const float4*)(xin + (size_t)(2 * row) * HW + pix0 + col);
        *(float4*)(Xs + row * TP + col) = xv;
        float4 cv = *(const float4*)(cpin + (size_t)(2 * row + 1) * HW + pix0 + col);
        *(float4*)(oo + (size_t)(2 * row + 1) * HW + pix0 + col) = cv;
    }
    __syncthreads();

    // --- GEMM: warp owns 8 output channels, lane owns 8 pixels (two float4 groups) ---
    const int warp  = tid >> 5;
    const int q     = tid & 31;
    const int obase = warp * 8;
    const int pA    = 4 * q;            // pixels [4q, 4q+4)
    const int pB    = 128 + 4 * q;      // pixels [128+4q, 128+4q+4)

    unsigned long long accA[8][2], accB[8][2];
    #pragma unroll
    for (int o = 0; o < 8; o++) {
        float bv = Bs[obase + o];
        unsigned long long bb = pk2(bv, bv);
        accA[o][0] = bb; accA[o][1] = bb;
        accB[o][0] = bb; accB[o][1] = bb;
    }

    #pragma unroll 8
    for (int c = 0; c < CH; c++) {
        const ulonglong2 xa = *(const ulonglong2*)(Xs + c * TP + pA);
        const ulonglong2 xb = *(const ulonglong2*)(Xs + c * TP + pB);
        const float2* wrow = Wd + c * CH + obase;
        #pragma unroll
        for (int j = 0; j < 4; j++) {
            ulonglong2 wv = *(const ulonglong2*)(wrow + 2 * j);  // {w[o],w[o]},{w[o+1],w[o+1]}
            FMA2(accA[2*j  ][0], wv.x, xa.x);
            FMA2(accA[2*j  ][1], wv.x, xa.y);
            FMA2(accB[2*j  ][0], wv.x, xb.x);
            FMA2(accB[2*j  ][1], wv.x, xb.y);
            FMA2(accA[2*j+1][0], wv.y, xa.x);
            FMA2(accA[2*j+1][1], wv.y, xa.y);
            FMA2(accB[2*j+1][0], wv.y, xb.x);
            FMA2(accB[2*j+1][1], wv.y, xb.y);
        }
    }

    // --- store even output channels, fully coalesced STG.128 ---
    #pragma unroll
    for (int o = 0; o < 8; o++) {
        size_t ch = (size_t)2 * (obase + o);
        *(ulonglong2*)(oo + ch * HW + pix0 + pA) = make_ulonglong2(accA[o][0], accA[o][1]);
        *(ulonglong2*)(oo + ch * HW + pix0 + pB) = make_ulonglong2(accB[o][0], accB[o][1]);
    }
}

extern "C" void kernel_launch(void* const* d_in, const int* in_sizes, int n_in,
                              void* d_out, int out_size)
{
    const float* lst = (const float*)d_in[0];
    const float* gui = (const float*)d_in[1];
    const float* w1  = (const float*)d_in[2];
    const float* b1  = (const float*)d_in[3];
    const float* w2  = (const float*)d_in[4];
    const float* b2  = (const float*)d_in[5];
    // d_in[6] is p (==2 for this problem instance; layout constants assume it)
    float* out = (float*)d_out;

    const size_t smem = (size_t)CH * TP * 4 + (size_t)CH * CH * 8 + CH * 4; // 98560 B
    cudaFuncSetAttribute(cx_kernel, cudaFuncAttributeMaxDynamicSharedMemorySize, (int)smem);

    dim3 grid(NCTA, 2);
    cx_kernel<<<grid, 256, smem>>>(lst, gui, w1, b1, w2, b2, out);
}

// round 3
// speedup vs baseline: 1.1342x; 1.1342x over previous
#include <cuda_runtime.h>

// ChannelExchangeWithConv: N=1, C=128, H=W=512, p=2
// out_lst = copy(lst); out_lst[::2] = W2 @ gui[::2] + b2
// out_gui = copy(gui); out_gui[::2] = W1 @ lst[::2] + b1

#define HW   262144
#define TP   256
#define NCTA (HW / TP)
#define CH   64

typedef unsigned long long u64;

__device__ __forceinline__ u64 pkdup(float x) {
    u64 r; asm("mov.b64 %0, {%1, %1};" : "=l"(r) : "f"(x)); return r;
}
__device__ __forceinline__ u64 pk2(float x, float y) {
    u64 r; asm("mov.b64 %0, {%1, %2};" : "=l"(r) : "f"(x), "f"(y)); return r;
}
__device__ __forceinline__ void unpk(u64 v, float& lo, float& hi) {
    asm("mov.b64 {%0, %1}, %2;" : "=f"(lo), "=f"(hi) : "l"(v));
}
// packed 2-wide fp32 fma: acc += a*b (two independent fp32 lanes)
#define FMA2(acc, a, b) \
    asm("fma.rn.f32x2 %0, %1, %2, %0;" : "+l"(acc) : "l"(a), "l"(b))

__global__ __launch_bounds__(256, 2)
void cx_kernel(const float* __restrict__ lst, const float* __restrict__ gui,
               const float* __restrict__ w1,  const float* __restrict__ b1,
               const float* __restrict__ w2,  const float* __restrict__ b2,
               float* __restrict__ out)
{
    extern __shared__ float smem[];
    float*  Xs = smem;                                  // [64][TP] conv-input tile
    float2* Wp = (float2*)(smem + CH * TP);             // [c][32] o-pair weights {w[2j],w[2j+1]}
    float*  Bs = (float*)(Wp + CH * 32);                // [64] bias

    const int   dir  = blockIdx.y;                      // 0: out_lst, 1: out_gui
    const float* xin  = dir ? lst : gui;                // conv input (even channels)
    const float* cpin = dir ? gui : lst;                // passthrough src (odd channels)
    const float* W    = dir ? w1 : w2;
    const float* B    = dir ? b1 : b2;
    float* oo = out + (size_t)dir * 128 * HW;

    const int pix0 = blockIdx.x * TP;
    const int tid  = threadIdx.x;

    // --- stage weights as o-pairs, transposed to [c][j]: Wp[c][j]={W[2j][c],W[2j+1][c]} ---
    #pragma unroll
    for (int i = 0; i < 8; i++) {
        int idx = i * 256 + tid;        // 0..2047
        int c = idx >> 5;               // 0..63
        int j = idx & 31;               // 0..31 (o-pair index)
        Wp[c * 32 + j] = make_float2(W[(2 * j) * CH + c], W[(2 * j + 1) * CH + c]);
    }
    if (tid < CH) Bs[tid] = B[tid];

    // --- stage even channels of xin into smem; stream odd-channel passthrough ---
    #pragma unroll
    for (int i = 0; i < 16; i++) {
        int idx = i * 256 + tid;        // float4 units over [64][64]
        int row = idx >> 6;             // masked-channel index 0..63
        int col = (idx & 63) << 2;      // float offset in tile
        float4 xv = *(const float4*)(xin + (size_t)(2 * row) * HW + pix0 + col);
        *(float4*)(Xs + row * TP + col) = xv;
        float4 cv = *(const float4*)(cpin + (size_t)(2 * row + 1) * HW + pix0 + col);
        *(float4*)(oo + (size_t)(2 * row + 1) * HW + pix0 + col) = cv;
    }
    __syncthreads();

    // --- GEMM: warp tile = 128 px x 16 o. 8 warps = 2 px-groups x 4 o-groups. ---
    // Thread tile: 4 px x 16 o, acc packed over o-pairs -> 32 f32x2 (64 regs).
    const int warp  = tid >> 5;
    const int q     = tid & 31;
    const int pxgrp = warp & 1;
    const int ogrp  = warp >> 1;
    const int px    = pxgrp * 128 + 4 * q;   // thread's 4 pixels
    const int jbase = ogrp * 8;              // 8 o-pairs -> conv o in [16*ogrp, 16*ogrp+16)

    u64 acc[4][8];
    #pragma unroll
    for (int j = 0; j < 8; j++) {
        u64 bb = pk2(Bs[2 * (jbase + j)], Bs[2 * (jbase + j) + 1]);
        acc[0][j] = bb; acc[1][j] = bb; acc[2][j] = bb; acc[3][j] = bb;
    }

    const float* xp = Xs + px;

    #pragma unroll 8
    for (int c = 0; c < CH; c++) {
        float4 xv = *(const float4*)(xp + c * TP);                 // 1 LDS.128 (distinct)
        u64 x0 = pkdup(xv.x), x1 = pkdup(xv.y), x2 = pkdup(xv.z), x3 = pkdup(xv.w);
        // row c of Wp = 32 float2 = 16 ull2; take this warp's 8 o-pairs = 4 ull2
        const ulonglong2* wr = (const ulonglong2*)(Wp + c * 32 + jbase);
        ulonglong2 wa = wr[0], wb = wr[1], wc2 = wr[2], wd = wr[3]; // 4 LDS.128 broadcast
        u64 w[8] = {wa.x, wa.y, wb.x, wb.y, wc2.x, wc2.y, wd.x, wd.y};
        #pragma unroll
        for (int j = 0; j < 8; j++) {
            FMA2(acc[0][j], w[j], x0);
            FMA2(acc[1][j], w[j], x1);
            FMA2(acc[2][j], w[j], x2);
            FMA2(acc[3][j], w[j], x3);
        }
    }

    // --- store: pair j holds conv outputs (2j', 2j'+1), j'=jbase+j -> global ch 4j', 4j'+2 ---
    #pragma unroll
    for (int j = 0; j < 8; j++) {
        float a0, a1, b0v, b1v, c0, c1, d0, d1;
        unpk(acc[0][j], a0, a1);
        unpk(acc[1][j], b0v, b1v);
        unpk(acc[2][j], c0, c1);
        unpk(acc[3][j], d0, d1);
        size_t ch0 = (size_t)4 * (jbase + j);
        size_t ch1 = ch0 + 2;
        *(float4*)(oo + ch0 * HW + pix0 + px) = make_float4(a0, b0v, c0, d0);
        *(float4*)(oo + ch1 * HW + pix0 + px) = make_float4(a1, b1v, c1, d1);
    }
}

extern "C" void kernel_launch(void* const* d_in, const int* in_sizes, int n_in,
                              void* d_out, int out_size)
{
    const float* lst = (const float*)d_in[0];
    const float* gui = (const float*)d_in[1];
    const float* w1  = (const float*)d_in[2];
    const float* b1  = (const float*)d_in[3];
    const float* w2  = (const float*)d_in[4];
    const float* b2  = (const float*)d_in[5];
    float* out = (float*)d_out;

    const size_t smem = (size_t)CH * TP * 4 + (size_t)CH * 32 * 8 + CH * 4; // 82176 B
    cudaFuncSetAttribute(cx_kernel, cudaFuncAttributeMaxDynamicSharedMemorySize, (int)smem);

    dim3 grid(NCTA, 2);
    cx_kernel<<<grid, 256, smem>>>(lst, gui, w1, b1, w2, b2, out);
}